// round 6
// baseline (speedup 1.0000x reference)
#include <cuda_runtime.h>

// Sparse CG tensor product:
//   out[b, M[i]] += scale[i] * x[b, M1[i]] * y[b, M2[i]]
//
// One CTA = 32 batch rows, 32 warps. Tiles in smem as [32 rows][stride 513]:
// gather addr = lane*513 + m -> bank (lane + m) mod 32, a permutation over
// lanes => conflict-free by construction. Odd stride => scalar fill/drain,
// lane -> consecutive d (conflict-free STS/LDS, coalesced LDG/STG).
//
// Path metadata {m*4, m1*4, m2*4, scale} is read with warp-uniform __ldg
// (one 16B sector per warp) -- no smem staging, no syncwarp. M sorted =>
// register accumulation, one smem store per column change; per-warp path
// ranges are segment-aligned => single writer per column, no atomics.

#define DIMC    512
#define STRIDE  513
#define TILE    (32 * STRIDE)          // 16416 floats
#define NWARP   32
#define NTHR    (NWARP * 32)           // 1024
#define MAXNNZ  8192

__device__ int4 g_paths[MAXNNZ];       // {M*4, M1*4, M2*4, bits(scale)}
__device__ int  g_wstart[NWARP + 1];

// ---------------------------------------------------------------------------
__global__ void pack_kernel(const float* __restrict__ scale,
                            const int* __restrict__ M,
                            const int* __restrict__ M1,
                            const int* __restrict__ M2,
                            int nnz)
{
    int i = blockIdx.x * blockDim.x + threadIdx.x;
    if (i < nnz) {
        g_paths[i] = make_int4(M[i] << 2, M1[i] << 2, M2[i] << 2,
                               __float_as_int(scale[i]));
    }
    if (i == 0) {
        g_wstart[0] = 0;
        g_wstart[NWARP] = nnz;
        int prev = 0;
        for (int w = 1; w < NWARP; w++) {
            int t = (int)(((long long)w * nnz) / NWARP);
            if (t < prev) t = prev;
            while (t > 0 && t < nnz && M[t] == M[t - 1]) t++;  // segment align
            g_wstart[w] = t;
            prev = t;
        }
    }
}

// ---------------------------------------------------------------------------
__global__ __launch_bounds__(NTHR, 1)
void tp_kernel(const float* __restrict__ x,
               const float* __restrict__ y,
               float* __restrict__ out,
               int Brows)
{
    extern __shared__ float sm[];
    float* xs = sm;                          // [32][STRIDE]
    float* ys = sm + TILE;
    float* os = sm + 2 * TILE;

    const int tid  = threadIdx.x;
    const int lane = tid & 31;
    const int warp = tid >> 5;
    const int b0   = blockIdx.x << 5;
    const int nb   = min(32, Brows - b0);

    // ---- fill tiles + zero output tile (scalar, conflict-free, coalesced) ----
    if (nb == 32) {
        const int gbase = b0 * DIMC;
        #pragma unroll 4
        for (int it = 0; it < (32 * DIMC) / NTHR; it++) {   // 16 iters
            int idx = it * NTHR + tid;
            int b = idx >> 9;
            int d = idx & 511;
            int s = b * STRIDE + d;
            xs[s] = x[gbase + idx];
            ys[s] = y[gbase + idx];
            os[s] = 0.f;
        }
    } else {
        for (int idx = tid; idx < 32 * DIMC; idx += NTHR) {
            int b = idx >> 9;
            int d = idx & 511;
            float vx = 0.f, vy = 0.f;
            if (b < nb) {
                int g = (b0 + b) * DIMC + d;
                vx = x[g];
                vy = y[g];
            }
            int s = b * STRIDE + d;
            xs[s] = vx;
            ys[s] = vy;
            os[s] = 0.f;
        }
    }
    __syncthreads();

    // ---- per-warp path processing ----
    const int istart = g_wstart[warp];
    const int iend   = g_wstart[warp + 1];

    if (istart < iend) {
        const char* xc = (const char*)xs + lane * (STRIDE * 4);
        const char* yc = (const char*)ys + lane * (STRIDE * 4);
        char*       oc = (char*)os       + lane * (STRIDE * 4);
        const int4* gp = g_paths;

        float acc  = 0.f;
        int   mcur = __ldg(&gp[istart]).x;

        int i = istart;
        const int nquad = (iend - istart) >> 2;
        for (int q = 0; q < nquad; q++, i += 4) {
            // 4 independent warp-uniform LDG.128 (compiler hoists them)
            int4 p0 = __ldg(&gp[i]);
            int4 p1 = __ldg(&gp[i + 1]);
            int4 p2 = __ldg(&gp[i + 2]);
            int4 p3 = __ldg(&gp[i + 3]);

            if (p0.x != mcur) { *(float*)(oc + mcur) = acc; acc = 0.f; mcur = p0.x; }
            acc = fmaf(__int_as_float(p0.w) * *(const float*)(xc + p0.y),
                       *(const float*)(yc + p0.z), acc);

            if (p1.x != mcur) { *(float*)(oc + mcur) = acc; acc = 0.f; mcur = p1.x; }
            acc = fmaf(__int_as_float(p1.w) * *(const float*)(xc + p1.y),
                       *(const float*)(yc + p1.z), acc);

            if (p2.x != mcur) { *(float*)(oc + mcur) = acc; acc = 0.f; mcur = p2.x; }
            acc = fmaf(__int_as_float(p2.w) * *(const float*)(xc + p2.y),
                       *(const float*)(yc + p2.z), acc);

            if (p3.x != mcur) { *(float*)(oc + mcur) = acc; acc = 0.f; mcur = p3.x; }
            acc = fmaf(__int_as_float(p3.w) * *(const float*)(xc + p3.y),
                       *(const float*)(yc + p3.z), acc);
        }
        for (; i < iend; i++) {           // remainder (0-3 paths)
            int4 p = __ldg(&gp[i]);
            if (p.x != mcur) { *(float*)(oc + mcur) = acc; acc = 0.f; mcur = p.x; }
            acc = fmaf(__int_as_float(p.w) * *(const float*)(xc + p.y),
                       *(const float*)(yc + p.z), acc);
        }
        *(float*)(oc + mcur) = acc;       // final flush
    }
    __syncthreads();

    // ---- drain output tile (scalar LDS, coalesced STG) ----
    if (nb == 32) {
        const int gbase = b0 * DIMC;
        #pragma unroll 4
        for (int it = 0; it < (32 * DIMC) / NTHR; it++) {
            int idx = it * NTHR + tid;
            int b = idx >> 9;
            int d = idx & 511;
            out[gbase + idx] = os[b * STRIDE + d];
        }
    } else {
        for (int idx = tid; idx < 32 * DIMC; idx += NTHR) {
            int b = idx >> 9;
            int d = idx & 511;
            if (b < nb) out[(b0 + b) * DIMC + d] = os[b * STRIDE + d];
        }
    }
}

// ---------------------------------------------------------------------------
extern "C" void kernel_launch(void* const* d_in, const int* in_sizes, int n_in,
                              void* d_out, int out_size)
{
    const float* x     = (const float*)d_in[0];
    const float* y     = (const float*)d_in[1];
    const float* scale = (const float*)d_in[2];
    const int*   M     = (const int*)d_in[3];
    const int*   M1    = (const int*)d_in[4];
    const int*   M2    = (const int*)d_in[5];
    float*       out   = (float*)d_out;

    const int B   = in_sizes[0] / DIMC;
    const int nnz = in_sizes[2];

    const size_t smem_bytes = (size_t)3 * TILE * sizeof(float);   // 196992 B
    cudaFuncSetAttribute(tp_kernel, cudaFuncAttributeMaxDynamicSharedMemorySize,
                         (int)smem_bytes);

    pack_kernel<<<(nnz + 255) / 256, 256>>>(scale, M, M1, M2, nnz);

    const int nblocks = (B + 31) / 32;
    tp_kernel<<<nblocks, NTHR, smem_bytes>>>(x, y, out, B);
}

// round 7
// speedup vs baseline: 1.1469x; 1.1469x over previous
#include <cuda_runtime.h>

// Sparse CG tensor product:
//   out[b, M[i]] += scale[i] * x[b, M1[i]] * y[b, M2[i]]
//
// One CTA = 32 batch rows, 32 warps. Tiles in smem as [32 rows][stride 513]:
// gather addr = lane*513 + m -> bank (lane + m) mod 32, a permutation over
// lanes => conflict-free. Odd stride => scalar fill/drain, lane -> consecutive
// d (conflict-free STS/LDS, coalesced LDG/STG).
//
// Path metadata is staged per-warp into smem (broadcast LDS.128 per path).
// Hot loop is fully branchless: flush-on-column-change is an inline-asm
// predicated st.shared + predicated acc reset (no BSSY/BSYNC, no BRA).
// M sorted => register accumulation; per-warp path ranges segment-aligned
// => single writer per output column, no atomics.

#define DIMC    512
#define STRIDE  513
#define TILE    (32 * STRIDE)          // 16416 floats
#define NWARP   32
#define NTHR    (NWARP * 32)           // 1024
#define CHUNK   32
#define MAXNNZ  8192

__device__ int4 g_paths[MAXNNZ];       // {M<<2, M1<<2, M2<<2, bits(scale)}
__device__ int  g_wstart[NWARP + 1];

// ---------------------------------------------------------------------------
__global__ void pack_kernel(const float* __restrict__ scale,
                            const int* __restrict__ M,
                            const int* __restrict__ M1,
                            const int* __restrict__ M2,
                            int nnz)
{
    int i = blockIdx.x * blockDim.x + threadIdx.x;
    if (i < nnz) {
        g_paths[i] = make_int4(M[i] << 2, M1[i] << 2, M2[i] << 2,
                               __float_as_int(scale[i]));
    }
    if (i == 0) {
        g_wstart[0] = 0;
        g_wstart[NWARP] = nnz;
        int prev = 0;
        for (int w = 1; w < NWARP; w++) {
            int t = (int)(((long long)w * nnz) / NWARP);
            if (t < prev) t = prev;
            while (t > 0 && t < nnz && M[t] == M[t - 1]) t++;  // segment align
            g_wstart[w] = t;
            prev = t;
        }
    }
}

// ---------------------------------------------------------------------------
__device__ __forceinline__ unsigned smem_u32(const void* p) {
    unsigned a;
    asm("{ .reg .u64 t; cvta.to.shared.u64 t, %1; cvt.u32.u64 %0, t; }"
        : "=r"(a) : "l"(p));
    return a;
}

__global__ __launch_bounds__(NTHR, 1)
void tp_kernel(const float* __restrict__ x,
               const float* __restrict__ y,
               float* __restrict__ out,
               int Brows)
{
    extern __shared__ float sm[];
    float* xs = sm;                          // [32][STRIDE]
    float* ys = sm + TILE;
    float* os = sm + 2 * TILE;
    int4*  spath = (int4*)(sm + 3 * TILE);   // [NWARP][CHUNK]

    const int tid  = threadIdx.x;
    const int lane = tid & 31;
    const int warp = tid >> 5;
    const int b0   = blockIdx.x << 5;
    const int nb   = min(32, Brows - b0);

    // ---- fill tiles + zero output tile (scalar, conflict-free, coalesced) ----
    if (nb == 32) {
        const int gbase = b0 * DIMC;
        #pragma unroll 4
        for (int it = 0; it < (32 * DIMC) / NTHR; it++) {   // 16 iters
            int idx = it * NTHR + tid;
            int b = idx >> 9;
            int d = idx & 511;
            int s = b * STRIDE + d;
            xs[s] = x[gbase + idx];
            ys[s] = y[gbase + idx];
            os[s] = 0.f;
        }
    } else {
        for (int idx = tid; idx < 32 * DIMC; idx += NTHR) {
            int b = idx >> 9;
            int d = idx & 511;
            float vx = 0.f, vy = 0.f;
            if (b < nb) {
                int g = (b0 + b) * DIMC + d;
                vx = x[g];
                vy = y[g];
            }
            int s = b * STRIDE + d;
            xs[s] = vx;
            ys[s] = vy;
            os[s] = 0.f;
        }
    }
    __syncthreads();

    // ---- per-warp path processing ----
    const int istart = g_wstart[warp];
    const int iend   = g_wstart[warp + 1];

    if (istart < iend) {
        int4* sp = spath + warp * CHUNK;

        // byte-offset bases into each tile for this lane's row
        const unsigned rowoff = (unsigned)(lane * STRIDE * 4);
        const unsigned xb = smem_u32(xs) + rowoff;
        const unsigned yb = smem_u32(ys) + rowoff;
        const unsigned ob = smem_u32(os) + rowoff;

        // prefetch chunk 0 (coalesced LDG.128, clamped + scale-zeroed)
        int4 r0;
        {
            int i0 = istart + lane;
            r0 = g_paths[min(i0, iend - 1)];
            if (i0 >= iend) r0.w = 0;
        }

        float acc  = 0.f;
        int   mcur = __shfl_sync(0xffffffffu, r0.x, 0);   // byte offset of first M

        for (int base = istart; base < iend; base += CHUNK) {
            sp[lane] = r0;
            __syncwarp();

            // prefetch next chunk (overlaps processing)
            {
                int i0 = base + CHUNK + lane;
                r0 = g_paths[min(max(i0, 0), iend - 1)];
                if (i0 >= iend) r0.w = 0;
            }

            #pragma unroll
            for (int j = 0; j < CHUNK; j++) {
                int4 p = sp[j];                 // broadcast LDS.128
                // branchless flush: @pp st.shared + @pp acc=0 (no BSSY/BRA)
                asm volatile(
                    "{ .reg .pred pp;\n\t"
                    "  setp.ne.s32 pp, %2, %3;\n\t"
                    "  @pp st.shared.f32 [%1], %0;\n\t"
                    "  @pp mov.f32 %0, 0f00000000; }"
                    : "+f"(acc)
                    : "r"(ob + (unsigned)mcur), "r"(p.x), "r"(mcur));
                mcur = p.x;
                acc = fmaf(__int_as_float(p.w)
                               * *(const float*)__cvta_shared_to_generic(
                                     (size_t)(xb + (unsigned)p.y)),
                           *(const float*)__cvta_shared_to_generic(
                                     (size_t)(yb + (unsigned)p.z)),
                           acc);
            }
            __syncwarp();
        }
        // final flush (segment-aligned ownership => plain store)
        asm volatile("st.shared.f32 [%0], %1;"
                     :: "r"(ob + (unsigned)mcur), "f"(acc));
    }
    __syncthreads();

    // ---- drain output tile (scalar LDS, coalesced STG) ----
    if (nb == 32) {
        const int gbase = b0 * DIMC;
        #pragma unroll 4
        for (int it = 0; it < (32 * DIMC) / NTHR; it++) {
            int idx = it * NTHR + tid;
            int b = idx >> 9;
            int d = idx & 511;
            out[gbase + idx] = os[b * STRIDE + d];
        }
    } else {
        for (int idx = tid; idx < 32 * DIMC; idx += NTHR) {
            int b = idx >> 9;
            int d = idx & 511;
            if (b < nb) out[(b0 + b) * DIMC + d] = os[b * STRIDE + d];
        }
    }
}

// ---------------------------------------------------------------------------
extern "C" void kernel_launch(void* const* d_in, const int* in_sizes, int n_in,
                              void* d_out, int out_size)
{
    const float* x     = (const float*)d_in[0];
    const float* y     = (const float*)d_in[1];
    const float* scale = (const float*)d_in[2];
    const int*   M     = (const int*)d_in[3];
    const int*   M1    = (const int*)d_in[4];
    const int*   M2    = (const int*)d_in[5];
    float*       out   = (float*)d_out;

    const int B   = in_sizes[0] / DIMC;
    const int nnz = in_sizes[2];

    const size_t smem_bytes = (size_t)3 * TILE * sizeof(float)
                            + (size_t)NWARP * CHUNK * sizeof(int4); // 213376 B
    cudaFuncSetAttribute(tp_kernel, cudaFuncAttributeMaxDynamicSharedMemorySize,
                         (int)smem_bytes);

    pack_kernel<<<(nnz + 255) / 256, 256>>>(scale, M, M1, M2, nnz);

    const int nblocks = (B + 31) / 32;
    tp_kernel<<<nblocks, NTHR, smem_bytes>>>(x, y, out, B);
}